// round 4
// baseline (speedup 1.0000x reference)
#include <cuda_runtime.h>
#include <math.h>

// Problem constants
// B=256, LAT=20, HID=128, G=25000, BIN=25, C=7, GB=1000
// Output layout (concatenated f32):
//   mu      [256,25000]      @ 0
//   theta   [256,25000]      @ 6,400,000
//   pi_drop [256,25000]      @ 12,800,000
//   sample  [256,25000]      @ 19,200,000
//   pi      [256,25000,7]    @ 25,600,000   (total 70,400,000)

static __device__ float g_x2[256 * 128];
static __device__ float g_logits[256 * 7000];     // rho logits [b][c*1000+o]

#define N_GEMM_BLK 784     // 98 gtiles x 8 btiles
#define N_SAMP_BLK 25088   // 98 gtiles x 256 b
#define INTERLEAVE 33      // 1 gemm block per 33 ids

// ---------------------------------------------------------------------------
// packed f32x2 helpers (Blackwell FFMA2 path)
// ---------------------------------------------------------------------------
__device__ __forceinline__ unsigned long long packf2(float lo, float hi) {
    unsigned long long r;
    asm("mov.b64 %0, {%1, %2};" : "=l"(r) : "f"(lo), "f"(hi));
    return r;
}
__device__ __forceinline__ float2 unpackf2(unsigned long long v) {
    float lo, hi;
    asm("mov.b64 {%0, %1}, %2;" : "=f"(lo), "=f"(hi) : "l"(v));
    return make_float2(lo, hi);
}
__device__ __forceinline__ void ffma2(unsigned long long& d, unsigned long long a,
                                      unsigned long long b) {
    asm("fma.rn.f32x2 %0, %1, %2, %0;" : "+l"(d) : "l"(a), "l"(b));
}

// ---------------------------------------------------------------------------
// Threefry-2x32, 20 rounds, key = (0, 42), partitionable mode
// ---------------------------------------------------------------------------
__device__ __forceinline__ void tf2x32(unsigned x0, unsigned x1,
                                       unsigned& o0, unsigned& o1) {
    const unsigned K0 = 0u;
    const unsigned K1 = 42u;
    const unsigned K2 = 0x1BD11BDAu ^ 0u ^ 42u;
    x0 += K0; x1 += K1;
#define TF_R(r) { x0 += x1; x1 = __funnelshift_l(x1, x1, r); x1 ^= x0; }
    TF_R(13) TF_R(15) TF_R(26) TF_R(6)
    x0 += K1; x1 += K2 + 1u;
    TF_R(17) TF_R(29) TF_R(16) TF_R(24)
    x0 += K2; x1 += K0 + 2u;
    TF_R(13) TF_R(15) TF_R(26) TF_R(6)
    x0 += K0; x1 += K1 + 3u;
    TF_R(17) TF_R(29) TF_R(16) TF_R(24)
    x0 += K1; x1 += K2 + 4u;
    TF_R(13) TF_R(15) TF_R(26) TF_R(6)
    x0 += K2; x1 += K0 + 5u;
#undef TF_R
    o0 = x0; o1 = x1;
}

__device__ __forceinline__ float bits_to_uniform(unsigned bits) {
    return __uint_as_float((bits >> 9) | 0x3f800000u) - 1.0f;
}

// ---------------------------------------------------------------------------
// Fused MLP: x2 = relu(bn(relu(bn(z@w0+b0)) @ w1 + b1))
// ---------------------------------------------------------------------------
__global__ void mlp_kernel(const float* __restrict__ z,
                           const float* __restrict__ w0, const float* __restrict__ b0,
                           const float* __restrict__ g0, const float* __restrict__ be0,
                           const float* __restrict__ m0, const float* __restrict__ v0,
                           const float* __restrict__ w1, const float* __restrict__ b1,
                           const float* __restrict__ g1, const float* __restrict__ be1,
                           const float* __restrict__ m1, const float* __restrict__ v1) {
    __shared__ float zr[20];
    __shared__ float xr[128];
    int b = blockIdx.x, h = threadIdx.x;
    if (h < 20) zr[h] = z[b * 20 + h];
    __syncthreads();
    float acc = b0[h];
#pragma unroll
    for (int k = 0; k < 20; k++) acc = fmaf(zr[k], w0[k * 128 + h], acc);
    acc = (acc - m0[h]) * rsqrtf(v0[h] + 1e-3f) * g0[h] + be0[h];
    xr[h] = fmaxf(acc, 0.f);
    __syncthreads();
    float acc2 = b1[h];
#pragma unroll 8
    for (int k = 0; k < 128; k++) acc2 = fmaf(xr[k], w1[k * 128 + h], acc2);
    acc2 = (acc2 - m1[h]) * rsqrtf(v1[h] + 1e-3f) * g1[h] + be1[h];
    g_x2[b * 128 + h] = fmaxf(acc2, 0.f);
}

// ---------------------------------------------------------------------------
// rho GEMM: logits[b][j] = x2[b] . wrho[c,:,o] + brho[c,o],  j = c*1000+o
// ---------------------------------------------------------------------------
__global__ void __launch_bounds__(256, 4)
rho_gemm_kernel(const float* __restrict__ wrho, const float* __restrict__ brho) {
    __shared__ unsigned long long xsp[128 * 8];
    int tid = threadIdx.x;
    int b0r = blockIdx.y * 16;
    for (int i = tid; i < 128 * 8; i += 256) {
        int k = i >> 3, i2 = i & 7;
        float lo = g_x2[(b0r + 2 * i2) * 128 + k];
        float hi = g_x2[(b0r + 2 * i2 + 1) * 128 + k];
        xsp[i] = packf2(lo, hi);
    }
    __syncthreads();
    int j = blockIdx.x * 256 + tid;
    if (j >= 7000) return;
    int c = j / 1000;
    int o = j - c * 1000;
    const float* wb = wrho + c * 128000 + o;
    unsigned long long acc[8];
    {
        float bv = brho[c * 1000 + o];
        unsigned long long b2 = packf2(bv, bv);
#pragma unroll
        for (int i = 0; i < 8; i++) acc[i] = b2;
    }
#pragma unroll 4
    for (int k = 0; k < 128; k++) {
        float wv = wb[k * 1000];
        unsigned long long w2 = packf2(wv, wv);
#pragma unroll
        for (int i = 0; i < 8; i++) ffma2(acc[i], xsp[k * 8 + i], w2);
    }
#pragma unroll
    for (int i = 0; i < 8; i++) {
        float2 t = unpackf2(acc[i]);
        g_logits[(b0r + 2 * i) * 7000 + j] = t.x;
        g_logits[(b0r + 2 * i + 1) * 7000 + j] = t.y;
    }
}

// ---------------------------------------------------------------------------
// MEGA kernel: block-role specialization.
//  role gemm  (784 blocks, 1 of every 33): theta/pi_drop FFMA2 GEMM
//  role sample(25088 blocks): inline rho-softmax + threefry gumbel argmax
// Roles are interleaved so long-running gemm blocks stay co-resident with
// alu-bound sample blocks (fma/alu pipe overlap; gemm L2 latency hidden).
// ---------------------------------------------------------------------------
union MegaSmem {
    unsigned long long xsp[128 * 16];                // gemm role: 16KB
    struct { float sp[12 * 7]; float spo[256 * 7]; } s;  // sample role
};

__global__ void __launch_bounds__(256, 2)
mega_kernel(const float* __restrict__ wr, const float* __restrict__ br,
            const float* __restrict__ wd, const float* __restrict__ bd,
            const float* __restrict__ ws, const float* __restrict__ bs,
            float* __restrict__ out) {
    __shared__ MegaSmem sm;
    int tid = threadIdx.x;
    int id = blockIdx.x;

    if (id % INTERLEAVE == 0) {
        // ---------------- GEMM role ----------------
        int gid = id / INTERLEAVE;          // 0..783
        int gx = gid % 98;
        int b0r = (gid / 98) * 32;
        for (int i = tid; i < 128 * 16; i += 256) {
            int k = i >> 4, i2 = i & 15;
            float lo = g_x2[(b0r + 2 * i2) * 128 + k];
            float hi = g_x2[(b0r + 2 * i2 + 1) * 128 + k];
            sm.xsp[i] = packf2(lo, hi);
        }
        __syncthreads();
        int g = gx * 256 + tid;
        if (g >= 25000) return;
        unsigned long long ar[16], ad[16];
        {
            float brv = br[g], bdv = bd[g];
            unsigned long long br2 = packf2(brv, brv), bd2 = packf2(bdv, bdv);
#pragma unroll
            for (int i = 0; i < 16; i++) { ar[i] = br2; ad[i] = bd2; }
        }
#pragma unroll 4
        for (int k = 0; k < 128; k++) {
            float wrv = wr[k * 25000 + g];
            float wdv = wd[k * 25000 + g];
            unsigned long long wr2 = packf2(wrv, wrv);
            unsigned long long wd2 = packf2(wdv, wdv);
#pragma unroll
            for (int i = 0; i < 16; i++) {
                unsigned long long xv = sm.xsp[k * 16 + i];
                ffma2(ar[i], xv, wr2);
                ffma2(ad[i], xv, wd2);
            }
        }
#pragma unroll
        for (int i = 0; i < 16; i++) {
            float2 tr = unpackf2(ar[i]);
            float2 td = unpackf2(ad[i]);
            out[6400000 + (b0r + 2 * i) * 25000 + g] = expf(tr.x);
            out[6400000 + (b0r + 2 * i + 1) * 25000 + g] = expf(tr.y);
            out[12800000 + (b0r + 2 * i) * 25000 + g] = td.x;
            out[12800000 + (b0r + 2 * i + 1) * 25000 + g] = td.y;
        }
    } else {
        // ---------------- SAMPLE role ----------------
        int sid = (id / INTERLEAVE) * (INTERLEAVE - 1) + (id % INTERLEAVE) - 1;
        int b = sid / 98;                    // 0..255
        int g0 = (sid % 98) * 256;
        int nvalid = min(256, 25000 - g0);
        int bin0 = g0 / 25;
        int nbins = (g0 + nvalid - 1) / 25 - bin0 + 1;  // <= 11
        int npl = nbins * 7;
        float* sp = sm.s.sp;
        float* spo = sm.s.spo;
        // load raw logits for this (b, bin range):  sp[bl*7+c] = logits[b][c*1000+bin0+bl]
        for (int i = tid; i < npl; i += 256) {
            int bl = i / 7, c = i - bl * 7;
            sp[i] = g_logits[b * 7000 + c * 1000 + bin0 + bl];
        }
        __syncthreads();
        // inline softmax over c per bin
        if (tid < nbins) {
            float v[7];
            float mx = -1e30f;
#pragma unroll
            for (int c = 0; c < 7; c++) { v[c] = sp[tid * 7 + c]; mx = fmaxf(mx, v[c]); }
            float s = 0.f;
#pragma unroll
            for (int c = 0; c < 7; c++) { v[c] = expf(v[c] - mx); s += v[c]; }
            float inv = 1.f / s;
#pragma unroll
            for (int c = 0; c < 7; c++) sp[tid * 7 + c] = v[c] * inv;
        }
        __syncthreads();
        if (tid < nvalid) {
            int g = g0 + tid;
            int binl = g / 25 - bin0;
            const float* p = &sp[binl * 7];
            unsigned base = (unsigned)(b * 25000 + g) * 7u;
            float r[7];
            float mv = -1e30f;
#pragma unroll
            for (int c = 0; c < 7; c++) {
                unsigned o0, o1;
                tf2x32(0u, base + (unsigned)c, o0, o1);
                float u = bits_to_uniform(o0 ^ o1);
                float w = 1e-20f - logf(u + 1e-20f);
                float pc = p[c];
                spo[tid * 7 + c] = pc;
                r[c] = (pc + 1e-20f) / w;
                mv = fmaxf(mv, r[c]);
            }
            float s = 0.f;
#pragma unroll
            for (int c = 0; c < 7; c++) {
                if (r[c] == mv) s += (float)c;
            }
            float wsg = ws[g], bsg = bs[g];
            out[b * 25000 + g] = 1.f / (1.f + expf(-(s * wsg + bsg)));
            out[19200000 + b * 25000 + g] = s;
        }
        __syncthreads();
        int tot = nvalid * 7;
        float* pib = out + 25600000u + (unsigned)(b * 25000 + g0) * 7u;
        for (int i = tid; i < tot; i += 256) {
            pib[i] = spo[i];
        }
    }
}

// ---------------------------------------------------------------------------
extern "C" void kernel_launch(void* const* d_in, const int* in_sizes, int n_in,
                              void* d_out, int out_size) {
    const float* z    = (const float*)d_in[0];
    const float* w0   = (const float*)d_in[1];
    const float* b0   = (const float*)d_in[2];
    const float* g0   = (const float*)d_in[3];
    const float* be0  = (const float*)d_in[4];
    const float* m0   = (const float*)d_in[5];
    const float* v0   = (const float*)d_in[6];
    const float* w1   = (const float*)d_in[7];
    const float* b1   = (const float*)d_in[8];
    const float* g1   = (const float*)d_in[9];
    const float* be1  = (const float*)d_in[10];
    const float* m1   = (const float*)d_in[11];
    const float* v1   = (const float*)d_in[12];
    const float* wr   = (const float*)d_in[13];
    const float* br   = (const float*)d_in[14];
    const float* wd   = (const float*)d_in[15];
    const float* bd   = (const float*)d_in[16];
    const float* wrho = (const float*)d_in[17];
    const float* brho = (const float*)d_in[18];
    const float* wsc  = (const float*)d_in[19];
    const float* bsc  = (const float*)d_in[20];
    float* out = (float*)d_out;

    mlp_kernel<<<256, 128>>>(z, w0, b0, g0, be0, m0, v0, w1, b1, g1, be1, m1, v1);
    rho_gemm_kernel<<<dim3(28, 16), 256>>>(wrho, brho);
    mega_kernel<<<N_GEMM_BLK + N_SAMP_BLK, 256>>>(wr, br, wd, bd, wsc, bsc, out);
}

// round 6
// speedup vs baseline: 1.0555x; 1.0555x over previous
#include <cuda_runtime.h>
#include <math.h>

// Problem constants
// B=256, LAT=20, HID=128, G=25000, BIN=25, C=7, GB=1000
// Output layout (concatenated f32):
//   mu      [256,25000]      @ 0
//   theta   [256,25000]      @ 6,400,000
//   pi_drop [256,25000]      @ 12,800,000
//   sample  [256,25000]      @ 19,200,000
//   pi      [256,25000,7]    @ 25,600,000   (total 70,400,000)

static __device__ float g_x2[256 * 128];
static __device__ float g_logits[256 * 7000];     // rho logits [b][c*1000+o]

// mega grid: gemm role = 2 matrices x 49 gtiles x 16 btiles = 1568 blocks
//            sample role = 98 gtiles x 256 b = 25088 blocks
// interleave 1:17  ->  total 1568*17 = 26656 blocks
#define N_TOT 26656
#define ILV 17

// ---------------------------------------------------------------------------
// packed f32x2 helpers (Blackwell FFMA2 path)
// ---------------------------------------------------------------------------
__device__ __forceinline__ unsigned long long packf2(float lo, float hi) {
    unsigned long long r;
    asm("mov.b64 %0, {%1, %2};" : "=l"(r) : "f"(lo), "f"(hi));
    return r;
}
__device__ __forceinline__ float2 unpackf2(unsigned long long v) {
    float lo, hi;
    asm("mov.b64 {%0, %1}, %2;" : "=f"(lo), "=f"(hi) : "l"(v));
    return make_float2(lo, hi);
}
__device__ __forceinline__ void ffma2(unsigned long long& d, unsigned long long a,
                                      unsigned long long b) {
    asm("fma.rn.f32x2 %0, %1, %2, %0;" : "+l"(d) : "l"(a), "l"(b));
}

// ---------------------------------------------------------------------------
// Threefry-2x32, 20 rounds, key = (0, 42), partitionable mode
// ---------------------------------------------------------------------------
__device__ __forceinline__ void tf2x32(unsigned x0, unsigned x1,
                                       unsigned& o0, unsigned& o1) {
    const unsigned K0 = 0u;
    const unsigned K1 = 42u;
    const unsigned K2 = 0x1BD11BDAu ^ 0u ^ 42u;
    x0 += K0; x1 += K1;
#define TF_R(r) { x0 += x1; x1 = __funnelshift_l(x1, x1, r); x1 ^= x0; }
    TF_R(13) TF_R(15) TF_R(26) TF_R(6)
    x0 += K1; x1 += K2 + 1u;
    TF_R(17) TF_R(29) TF_R(16) TF_R(24)
    x0 += K2; x1 += K0 + 2u;
    TF_R(13) TF_R(15) TF_R(26) TF_R(6)
    x0 += K0; x1 += K1 + 3u;
    TF_R(17) TF_R(29) TF_R(16) TF_R(24)
    x0 += K1; x1 += K2 + 4u;
    TF_R(13) TF_R(15) TF_R(26) TF_R(6)
    x0 += K2; x1 += K0 + 5u;
#undef TF_R
    o0 = x0; o1 = x1;
}

__device__ __forceinline__ float bits_to_uniform(unsigned bits) {
    return __uint_as_float((bits >> 9) | 0x3f800000u) - 1.0f;
}

// ---------------------------------------------------------------------------
// Fused MLP: x2 = relu(bn(relu(bn(z@w0+b0)) @ w1 + b1))
// ---------------------------------------------------------------------------
__global__ void mlp_kernel(const float* __restrict__ z,
                           const float* __restrict__ w0, const float* __restrict__ b0,
                           const float* __restrict__ g0, const float* __restrict__ be0,
                           const float* __restrict__ m0, const float* __restrict__ v0,
                           const float* __restrict__ w1, const float* __restrict__ b1,
                           const float* __restrict__ g1, const float* __restrict__ be1,
                           const float* __restrict__ m1, const float* __restrict__ v1) {
    __shared__ float zr[20];
    __shared__ float xr[128];
    int b = blockIdx.x, h = threadIdx.x;
    if (h < 20) zr[h] = z[b * 20 + h];
    __syncthreads();
    float acc = b0[h];
#pragma unroll
    for (int k = 0; k < 20; k++) acc = fmaf(zr[k], w0[k * 128 + h], acc);
    acc = (acc - m0[h]) * rsqrtf(v0[h] + 1e-3f) * g0[h] + be0[h];
    xr[h] = fmaxf(acc, 0.f);
    __syncthreads();
    float acc2 = b1[h];
#pragma unroll 16
    for (int k = 0; k < 128; k++) acc2 = fmaf(xr[k], w1[k * 128 + h], acc2);
    acc2 = (acc2 - m1[h]) * rsqrtf(v1[h] + 1e-3f) * g1[h] + be1[h];
    g_x2[b * 128 + h] = fmaxf(acc2, 0.f);
}

// ---------------------------------------------------------------------------
// rho GEMM: logits[b][j] = x2[b] . wrho[c,:,o] + brho[c,o],  j = c*1000+o
// ---------------------------------------------------------------------------
__global__ void __launch_bounds__(256, 4)
rho_gemm_kernel(const float* __restrict__ wrho, const float* __restrict__ brho) {
    __shared__ unsigned long long xsp[128 * 8];
    int tid = threadIdx.x;
    int b0r = blockIdx.y * 16;
    for (int i = tid; i < 128 * 8; i += 256) {
        int k = i >> 3, i2 = i & 7;
        float lo = g_x2[(b0r + 2 * i2) * 128 + k];
        float hi = g_x2[(b0r + 2 * i2 + 1) * 128 + k];
        xsp[i] = packf2(lo, hi);
    }
    __syncthreads();
    int j = blockIdx.x * 256 + tid;
    if (j >= 7000) return;
    int c = j / 1000;
    int o = j - c * 1000;
    const float* wb = wrho + c * 128000 + o;
    unsigned long long acc[8];
    {
        float bv = brho[c * 1000 + o];
        unsigned long long b2 = packf2(bv, bv);
#pragma unroll
        for (int i = 0; i < 8; i++) acc[i] = b2;
    }
#pragma unroll 4
    for (int k = 0; k < 128; k++) {
        float wv = wb[k * 1000];
        unsigned long long w2 = packf2(wv, wv);
#pragma unroll
        for (int i = 0; i < 8; i++) ffma2(acc[i], xsp[k * 8 + i], w2);
    }
#pragma unroll
    for (int i = 0; i < 8; i++) {
        float2 t = unpackf2(acc[i]);
        g_logits[(b0r + 2 * i) * 7000 + j] = t.x;
        g_logits[(b0r + 2 * i + 1) * 7000 + j] = t.y;
    }
}

// ---------------------------------------------------------------------------
// MEGA kernel v2, lean registers.
//   gemm role (1/17 of blocks): ONE matrix (theta OR pi_drop), thread owns a
//     g-pair; weights load as naturally-packed float2; x pre-duplicated in
//     smem -> acc[16] u64 only (32 regs).
//   sample role: inline rho-softmax + threefry gumbel, cross-mult argmax
//     (no fp32 divisions).
// ---------------------------------------------------------------------------
union MegaSmem {
    unsigned long long xdup[128 * 16];                   // gemm: (x,x) per [k][b] 16KB
    struct { float sp[12 * 7]; float spo[256 * 7]; } s;  // sample
};

__global__ void __launch_bounds__(256, 4)
mega_kernel(const float* __restrict__ wr, const float* __restrict__ br,
            const float* __restrict__ wd, const float* __restrict__ bd,
            const float* __restrict__ ws, const float* __restrict__ bs,
            float* __restrict__ out) {
    __shared__ MegaSmem sm;
    int tid = threadIdx.x;
    int id = blockIdx.x;

    if (id % ILV == 0) {
        // ---------------- GEMM role ----------------
        int gid = id / ILV;             // 0..1567
        int which = gid & 1;            // 0 = theta, 1 = pi_drop
        int tile = gid >> 1;            // 0..783
        int gx = tile % 49;
        int b0r = (tile / 49) * 16;
        // fill duplicated-x smem: xdup[k*16+i] = (x2[b0r+i][k], x2[b0r+i][k])
        for (int t = tid; t < 2048; t += 256) {
            int k = t >> 4, i = t & 15;
            float xv = g_x2[(b0r + i) * 128 + k];
            sm.xdup[t] = packf2(xv, xv);
        }
        __syncthreads();
        int g = gx * 512 + 2 * tid;
        if (g >= 25000) return;
        const float* wsel = which ? wd : wr;
        const float* bsel = which ? bd : br;
        unsigned long long acc[16];
        {
            unsigned long long b2 = *(const unsigned long long*)(bsel + g);
#pragma unroll
            for (int i = 0; i < 16; i++) acc[i] = b2;
        }
        const float* wp = wsel + g;
#pragma unroll 2
        for (int k = 0; k < 128; k++) {
            unsigned long long w2 = *(const unsigned long long*)(wp + k * 25000);
            const ulonglong2* xv = (const ulonglong2*)&sm.xdup[k * 16];
#pragma unroll
            for (int i2 = 0; i2 < 8; i2++) {
                ulonglong2 x2p = xv[i2];
                ffma2(acc[2 * i2], x2p.x, w2);
                ffma2(acc[2 * i2 + 1], x2p.y, w2);
            }
        }
        if (which == 0) {
#pragma unroll
            for (int i = 0; i < 16; i++) {
                float2 t = unpackf2(acc[i]);
                *(float2*)&out[6400000 + (b0r + i) * 25000 + g] =
                    make_float2(expf(t.x), expf(t.y));
            }
        } else {
#pragma unroll
            for (int i = 0; i < 16; i++) {
                *(unsigned long long*)&out[12800000 + (b0r + i) * 25000 + g] = acc[i];
            }
        }
    } else {
        // ---------------- SAMPLE role ----------------
        int sid = (id / ILV) * (ILV - 1) + (id % ILV) - 1;  // 0..25087
        int b = sid / 98;                    // 0..255
        int g0 = (sid % 98) * 256;
        int nvalid = min(256, 25000 - g0);
        int bin0 = g0 / 25;
        int nbins = (g0 + nvalid - 1) / 25 - bin0 + 1;  // <= 11
        int npl = nbins * 7;
        float* sp = sm.s.sp;
        float* spo = sm.s.spo;
        for (int i = tid; i < npl; i += 256) {
            int bl = i / 7, c = i - bl * 7;
            sp[i] = g_logits[b * 7000 + c * 1000 + bin0 + bl];
        }
        __syncthreads();
        if (tid < nbins) {
            float v[7];
            float mx = -1e30f;
#pragma unroll
            for (int c = 0; c < 7; c++) { v[c] = sp[tid * 7 + c]; mx = fmaxf(mx, v[c]); }
            float s = 0.f;
#pragma unroll
            for (int c = 0; c < 7; c++) { v[c] = expf(v[c] - mx); s += v[c]; }
            float inv = 1.f / s;
#pragma unroll
            for (int c = 0; c < 7; c++) sp[tid * 7 + c] = v[c] * inv;
        }
        __syncthreads();
        if (tid < nvalid) {
            int g = g0 + tid;
            int binl = g / 25 - bin0;
            const float* p = &sp[binl * 7];
            unsigned base = (unsigned)(b * 25000 + g) * 7u;
            float a[7], w[7];
#pragma unroll
            for (int c = 0; c < 7; c++) {
                unsigned o0, o1;
                tf2x32(0u, base + (unsigned)c, o0, o1);
                float u = bits_to_uniform(o0 ^ o1);
                w[c] = 1e-20f - logf(u + 1e-20f);   // > 0
                float pc = p[c];
                spo[tid * 7 + c] = pc;
                a[c] = pc + 1e-20f;                  // > 0
            }
            // argmax of a/w via cross-multiplication (w > 0)
            int bb = 0;
#pragma unroll
            for (int c = 1; c < 7; c++) {
                if (a[c] * w[bb] > a[bb] * w[c]) bb = c;
            }
            float abb = a[bb], wbb = w[bb];
            float s = 0.f;
#pragma unroll
            for (int c = 0; c < 7; c++) {
                if (a[c] * wbb == abb * w[c]) s += (float)c;
            }
            float wsg = ws[g], bsg = bs[g];
            out[b * 25000 + g] = 1.f / (1.f + expf(-(s * wsg + bsg)));
            out[19200000 + b * 25000 + g] = s;
        }
        __syncthreads();
        int tot = nvalid * 7;
        float* pib = out + 25600000u + (unsigned)(b * 25000 + g0) * 7u;
        for (int i = tid; i < tot; i += 256) {
            pib[i] = spo[i];
        }
    }
}

// ---------------------------------------------------------------------------
extern "C" void kernel_launch(void* const* d_in, const int* in_sizes, int n_in,
                              void* d_out, int out_size) {
    const float* z    = (const float*)d_in[0];
    const float* w0   = (const float*)d_in[1];
    const float* b0   = (const float*)d_in[2];
    const float* g0   = (const float*)d_in[3];
    const float* be0  = (const float*)d_in[4];
    const float* m0   = (const float*)d_in[5];
    const float* v0   = (const float*)d_in[6];
    const float* w1   = (const float*)d_in[7];
    const float* b1   = (const float*)d_in[8];
    const float* g1   = (const float*)d_in[9];
    const float* be1  = (const float*)d_in[10];
    const float* m1   = (const float*)d_in[11];
    const float* v1   = (const float*)d_in[12];
    const float* wr   = (const float*)d_in[13];
    const float* br   = (const float*)d_in[14];
    const float* wd   = (const float*)d_in[15];
    const float* bd   = (const float*)d_in[16];
    const float* wrho = (const float*)d_in[17];
    const float* brho = (const float*)d_in[18];
    const float* wsc  = (const float*)d_in[19];
    const float* bsc  = (const float*)d_in[20];
    float* out = (float*)d_out;

    mlp_kernel<<<256, 128>>>(z, w0, b0, g0, be0, m0, v0, w1, b1, g1, be1, m1, v1);
    rho_gemm_kernel<<<dim3(28, 16), 256>>>(wrho, brho);
    mega_kernel<<<N_TOT, 256>>>(wr, br, wd, bd, wsc, bsc, out);
}

// round 7
// speedup vs baseline: 1.1981x; 1.1350x over previous
#include <cuda_runtime.h>
#include <math.h>

// Problem constants
// B=256, LAT=20, HID=128, G=25000, BIN=25, C=7, GB=1000
// Output layout (concatenated f32):
//   mu      [256,25000]      @ 0
//   theta   [256,25000]      @ 6,400,000
//   pi_drop [256,25000]      @ 12,800,000
//   sample  [256,25000]      @ 19,200,000
//   pi      [256,25000,7]    @ 25,600,000   (total 70,400,000)

static __device__ float g_x2[256 * 128];
static __device__ float g_logits[256 * 7000];     // rho logits [b][c*1000+o]

// ---------------------------------------------------------------------------
// packed f32x2 helpers (Blackwell FFMA2 path)
// ---------------------------------------------------------------------------
__device__ __forceinline__ unsigned long long packf2(float lo, float hi) {
    unsigned long long r;
    asm("mov.b64 %0, {%1, %2};" : "=l"(r) : "f"(lo), "f"(hi));
    return r;
}
__device__ __forceinline__ float2 unpackf2(unsigned long long v) {
    float lo, hi;
    asm("mov.b64 {%0, %1}, %2;" : "=f"(lo), "=f"(hi) : "l"(v));
    return make_float2(lo, hi);
}
__device__ __forceinline__ void ffma2(unsigned long long& d, unsigned long long a,
                                      unsigned long long b) {
    asm("fma.rn.f32x2 %0, %1, %2, %0;" : "+l"(d) : "l"(a), "l"(b));
}

// ---------------------------------------------------------------------------
// Threefry-2x32, 20 rounds, key = (0, 42), partitionable mode
// ---------------------------------------------------------------------------
__device__ __forceinline__ void tf2x32(unsigned x0, unsigned x1,
                                       unsigned& o0, unsigned& o1) {
    const unsigned K0 = 0u;
    const unsigned K1 = 42u;
    const unsigned K2 = 0x1BD11BDAu ^ 0u ^ 42u;
    x0 += K0; x1 += K1;
#define TF_R(r) { x0 += x1; x1 = __funnelshift_l(x1, x1, r); x1 ^= x0; }
    TF_R(13) TF_R(15) TF_R(26) TF_R(6)
    x0 += K1; x1 += K2 + 1u;
    TF_R(17) TF_R(29) TF_R(16) TF_R(24)
    x0 += K2; x1 += K0 + 2u;
    TF_R(13) TF_R(15) TF_R(26) TF_R(6)
    x0 += K0; x1 += K1 + 3u;
    TF_R(17) TF_R(29) TF_R(16) TF_R(24)
    x0 += K1; x1 += K2 + 4u;
    TF_R(13) TF_R(15) TF_R(26) TF_R(6)
    x0 += K2; x1 += K0 + 5u;
#undef TF_R
    o0 = x0; o1 = x1;
}

__device__ __forceinline__ float bits_to_uniform(unsigned bits) {
    return __uint_as_float((bits >> 9) | 0x3f800000u) - 1.0f;
}

// ---------------------------------------------------------------------------
// Fused MLP: x2 = relu(bn(relu(bn(z@w0+b0)) @ w1 + b1))
// ---------------------------------------------------------------------------
__global__ void mlp_kernel(const float* __restrict__ z,
                           const float* __restrict__ w0, const float* __restrict__ b0,
                           const float* __restrict__ g0, const float* __restrict__ be0,
                           const float* __restrict__ m0, const float* __restrict__ v0,
                           const float* __restrict__ w1, const float* __restrict__ b1,
                           const float* __restrict__ g1, const float* __restrict__ be1,
                           const float* __restrict__ m1, const float* __restrict__ v1) {
    __shared__ float zr[20];
    __shared__ float xr[128];
    int b = blockIdx.x, h = threadIdx.x;
    if (h < 20) zr[h] = z[b * 20 + h];
    __syncthreads();
    float acc = b0[h];
#pragma unroll
    for (int k = 0; k < 20; k++) acc = fmaf(zr[k], w0[k * 128 + h], acc);
    acc = (acc - m0[h]) * rsqrtf(v0[h] + 1e-3f) * g0[h] + be0[h];
    xr[h] = fmaxf(acc, 0.f);
    __syncthreads();
    float acc2 = b1[h];
#pragma unroll 16
    for (int k = 0; k < 128; k++) acc2 = fmaf(xr[k], w1[k * 128 + h], acc2);
    acc2 = (acc2 - m1[h]) * rsqrtf(v1[h] + 1e-3f) * g1[h] + be1[h];
    g_x2[b * 128 + h] = fmaxf(acc2, 0.f);
}

// ---------------------------------------------------------------------------
// rho GEMM: logits[b][j] = x2[b] . wrho[c,:,o] + brho[c,o],  j = c*1000+o
// ---------------------------------------------------------------------------
__global__ void __launch_bounds__(256, 4)
rho_gemm_kernel(const float* __restrict__ wrho, const float* __restrict__ brho) {
    __shared__ unsigned long long xsp[128 * 8];
    int tid = threadIdx.x;
    int b0r = blockIdx.y * 16;
    for (int i = tid; i < 128 * 8; i += 256) {
        int k = i >> 3, i2 = i & 7;
        float lo = g_x2[(b0r + 2 * i2) * 128 + k];
        float hi = g_x2[(b0r + 2 * i2 + 1) * 128 + k];
        xsp[i] = packf2(lo, hi);
    }
    __syncthreads();
    int j = blockIdx.x * 256 + tid;
    if (j >= 7000) return;
    int c = j / 1000;
    int o = j - c * 1000;
    const float* wb = wrho + c * 128000 + o;
    unsigned long long acc[8];
    {
        float bv = brho[c * 1000 + o];
        unsigned long long b2 = packf2(bv, bv);
#pragma unroll
        for (int i = 0; i < 8; i++) acc[i] = b2;
    }
#pragma unroll 4
    for (int k = 0; k < 128; k++) {
        float wv = wb[k * 1000];
        unsigned long long w2 = packf2(wv, wv);
#pragma unroll
        for (int i = 0; i < 8; i++) ffma2(acc[i], xsp[k * 8 + i], w2);
    }
#pragma unroll
    for (int i = 0; i < 8; i++) {
        float2 t = unpackf2(acc[i]);
        g_logits[(b0r + 2 * i) * 7000 + j] = t.x;
        g_logits[(b0r + 2 * i + 1) * 7000 + j] = t.y;
    }
}

// ---------------------------------------------------------------------------
// theta / pi_drop GEMM, lean-register version.
// blockIdx.z selects matrix (0 = theta w/ exp, 1 = pi_drop).
// Thread owns a g-pair -> weight float2 loads are naturally packed f32x2.
// x duplicated into smem as (x,x) pairs; acc[16] u64 = 32 regs only.
// grid (49, 16, 2), block 256, occ 4.
// ---------------------------------------------------------------------------
__global__ void __launch_bounds__(256, 4)
big_gemm_kernel(const float* __restrict__ wr, const float* __restrict__ br,
                const float* __restrict__ wd, const float* __restrict__ bd,
                float* __restrict__ out) {
    __shared__ unsigned long long xdup[128 * 16];   // [k][i] = (x,x)
    int tid = threadIdx.x;
    int b0r = blockIdx.y * 16;
    int which = blockIdx.z;
    for (int t = tid; t < 2048; t += 256) {
        int k = t >> 4, i = t & 15;
        float xv = g_x2[(b0r + i) * 128 + k];
        xdup[t] = packf2(xv, xv);
    }
    __syncthreads();
    int g = blockIdx.x * 512 + 2 * tid;
    if (g >= 25000) return;
    const float* wsel = which ? wd : wr;
    const float* bsel = which ? bd : br;
    unsigned long long acc[16];
    {
        unsigned long long b2 = *(const unsigned long long*)(bsel + g);
#pragma unroll
        for (int i = 0; i < 16; i++) acc[i] = b2;
    }
    const float* wp = wsel + g;
#pragma unroll 4
    for (int k = 0; k < 128; k++) {
        unsigned long long w2 = *(const unsigned long long*)(wp + k * 25000);
        const ulonglong2* xv = (const ulonglong2*)&xdup[k * 16];
#pragma unroll
        for (int i2 = 0; i2 < 8; i2++) {
            ulonglong2 x2p = xv[i2];
            ffma2(acc[2 * i2], x2p.x, w2);
            ffma2(acc[2 * i2 + 1], x2p.y, w2);
        }
    }
    if (which == 0) {
#pragma unroll
        for (int i = 0; i < 16; i++) {
            float2 t = unpackf2(acc[i]);
            *(float2*)&out[6400000 + (b0r + i) * 25000 + g] =
                make_float2(expf(t.x), expf(t.y));
        }
    } else {
#pragma unroll
        for (int i = 0; i < 16; i++) {
            *(unsigned long long*)&out[12800000 + (b0r + i) * 25000 + g] = acc[i];
        }
    }
}

// ---------------------------------------------------------------------------
// Sample kernel: inline rho-softmax (from raw logits) + threefry gumbel
// argmax via cross-multiplication (no fp32 division), mu + sample + pi out.
// grid (98, 256), block 256.
// ---------------------------------------------------------------------------
__global__ void __launch_bounds__(256)
sample_kernel(const float* __restrict__ ws, const float* __restrict__ bs,
              float* __restrict__ out) {
    __shared__ float sp[12 * 7];
    __shared__ float spo[256 * 7];
    int tid = threadIdx.x;
    int g0 = blockIdx.x * 256;
    int b = blockIdx.y;                  // 0..255
    int nvalid = min(256, 25000 - g0);
    int bin0 = g0 / 25;
    int nbins = (g0 + nvalid - 1) / 25 - bin0 + 1;  // <= 11
    int npl = nbins * 7;
    for (int i = tid; i < npl; i += 256) {
        int bl = i / 7, c = i - bl * 7;
        sp[i] = g_logits[b * 7000 + c * 1000 + bin0 + bl];
    }
    __syncthreads();
    if (tid < nbins) {
        float v[7];
        float mx = -1e30f;
#pragma unroll
        for (int c = 0; c < 7; c++) { v[c] = sp[tid * 7 + c]; mx = fmaxf(mx, v[c]); }
        float s = 0.f;
#pragma unroll
        for (int c = 0; c < 7; c++) { v[c] = expf(v[c] - mx); s += v[c]; }
        float inv = 1.f / s;
#pragma unroll
        for (int c = 0; c < 7; c++) sp[tid * 7 + c] = v[c] * inv;
    }
    __syncthreads();
    if (tid < nvalid) {
        int g = g0 + tid;
        int binl = g / 25 - bin0;
        const float* p = &sp[binl * 7];
        unsigned base = (unsigned)(b * 25000 + g) * 7u;
        float a[7], w[7];
#pragma unroll
        for (int c = 0; c < 7; c++) {
            unsigned o0, o1;
            tf2x32(0u, base + (unsigned)c, o0, o1);
            float u = bits_to_uniform(o0 ^ o1);
            w[c] = 1e-20f - logf(u + 1e-20f);   // > 0
            float pc = p[c];
            spo[tid * 7 + c] = pc;
            a[c] = pc + 1e-20f;                  // > 0
        }
        // argmax of a/w via cross-multiplication (w > 0)
        int bb = 0;
#pragma unroll
        for (int c = 1; c < 7; c++) {
            if (a[c] * w[bb] > a[bb] * w[c]) bb = c;
        }
        float abb = a[bb], wbb = w[bb];
        float s = 0.f;
#pragma unroll
        for (int c = 0; c < 7; c++) {
            if (a[c] * wbb == abb * w[c]) s += (float)c;
        }
        float wsg = ws[g], bsg = bs[g];
        out[b * 25000 + g] = 1.f / (1.f + expf(-(s * wsg + bsg)));
        out[19200000 + b * 25000 + g] = s;
    }
    __syncthreads();
    int tot = nvalid * 7;
    float* pib = out + 25600000u + (unsigned)(b * 25000 + g0) * 7u;
    for (int i = tid; i < tot; i += 256) {
        pib[i] = spo[i];
    }
}

// ---------------------------------------------------------------------------
extern "C" void kernel_launch(void* const* d_in, const int* in_sizes, int n_in,
                              void* d_out, int out_size) {
    const float* z    = (const float*)d_in[0];
    const float* w0   = (const float*)d_in[1];
    const float* b0   = (const float*)d_in[2];
    const float* g0   = (const float*)d_in[3];
    const float* be0  = (const float*)d_in[4];
    const float* m0   = (const float*)d_in[5];
    const float* v0   = (const float*)d_in[6];
    const float* w1   = (const float*)d_in[7];
    const float* b1   = (const float*)d_in[8];
    const float* g1   = (const float*)d_in[9];
    const float* be1  = (const float*)d_in[10];
    const float* m1   = (const float*)d_in[11];
    const float* v1   = (const float*)d_in[12];
    const float* wr   = (const float*)d_in[13];
    const float* br   = (const float*)d_in[14];
    const float* wd   = (const float*)d_in[15];
    const float* bd   = (const float*)d_in[16];
    const float* wrho = (const float*)d_in[17];
    const float* brho = (const float*)d_in[18];
    const float* wsc  = (const float*)d_in[19];
    const float* bsc  = (const float*)d_in[20];
    float* out = (float*)d_out;

    mlp_kernel<<<256, 128>>>(z, w0, b0, g0, be0, m0, v0, w1, b1, g1, be1, m1, v1);
    rho_gemm_kernel<<<dim3(28, 16), 256>>>(wrho, brho);
    big_gemm_kernel<<<dim3(49, 16, 2), 256>>>(wr, br, wd, bd, out);
    sample_kernel<<<dim3(98, 256), 256>>>(wsc, bsc, out);
}

// round 8
// speedup vs baseline: 1.3532x; 1.1295x over previous
#include <cuda_runtime.h>
#include <math.h>

// Problem constants
// B=256, LAT=20, HID=128, G=25000, BIN=25, C=7, GB=1000
// Output layout (concatenated f32):
//   mu      [256,25000]      @ 0
//   theta   [256,25000]      @ 6,400,000
//   pi_drop [256,25000]      @ 12,800,000
//   sample  [256,25000]      @ 19,200,000
//   pi      [256,25000,7]    @ 25,600,000   (total 70,400,000)

static __device__ float g_x2[256 * 128];
static __device__ float g_logits[256 * 7000];     // rho logits [b][c*1000+o]

// Side stream + events for gemm/sample overlap. Created once at process start
// (static ctor runs before harness capture; streams/events are context
// resources, not device memory allocations).
namespace {
struct HxStreams {
    cudaStream_t s1 = nullptr;
    cudaEvent_t e0 = nullptr, e1 = nullptr;
    HxStreams() {
        cudaStreamCreateWithFlags(&s1, cudaStreamNonBlocking);
        cudaEventCreateWithFlags(&e0, cudaEventDisableTiming);
        cudaEventCreateWithFlags(&e1, cudaEventDisableTiming);
    }
};
HxStreams g_sx;
}

// ---------------------------------------------------------------------------
// packed f32x2 helpers
// ---------------------------------------------------------------------------
__device__ __forceinline__ unsigned long long packf2(float lo, float hi) {
    unsigned long long r;
    asm("mov.b64 %0, {%1, %2};" : "=l"(r) : "f"(lo), "f"(hi));
    return r;
}
__device__ __forceinline__ float2 unpackf2(unsigned long long v) {
    float lo, hi;
    asm("mov.b64 {%0, %1}, %2;" : "=f"(lo), "=f"(hi) : "l"(v));
    return make_float2(lo, hi);
}
__device__ __forceinline__ void ffma2(unsigned long long& d, unsigned long long a,
                                      unsigned long long b) {
    asm("fma.rn.f32x2 %0, %1, %2, %0;" : "+l"(d) : "l"(a), "l"(b));
}

// ---------------------------------------------------------------------------
// Threefry-2x32, 20 rounds, key = (0, 42), partitionable mode
// ---------------------------------------------------------------------------
__device__ __forceinline__ void tf2x32(unsigned x0, unsigned x1,
                                       unsigned& o0, unsigned& o1) {
    const unsigned K0 = 0u;
    const unsigned K1 = 42u;
    const unsigned K2 = 0x1BD11BDAu ^ 0u ^ 42u;
    x0 += K0; x1 += K1;
#define TF_R(r) { x0 += x1; x1 = __funnelshift_l(x1, x1, r); x1 ^= x0; }
    TF_R(13) TF_R(15) TF_R(26) TF_R(6)
    x0 += K1; x1 += K2 + 1u;
    TF_R(17) TF_R(29) TF_R(16) TF_R(24)
    x0 += K2; x1 += K0 + 2u;
    TF_R(13) TF_R(15) TF_R(26) TF_R(6)
    x0 += K0; x1 += K1 + 3u;
    TF_R(17) TF_R(29) TF_R(16) TF_R(24)
    x0 += K1; x1 += K2 + 4u;
    TF_R(13) TF_R(15) TF_R(26) TF_R(6)
    x0 += K2; x1 += K0 + 5u;
#undef TF_R
    o0 = x0; o1 = x1;
}

__device__ __forceinline__ float bits_to_uniform(unsigned bits) {
    return __uint_as_float((bits >> 9) | 0x3f800000u) - 1.0f;
}

// ---------------------------------------------------------------------------
// Fused MLP: x2 = relu(bn(relu(bn(z@w0+b0)) @ w1 + b1))
// ---------------------------------------------------------------------------
__global__ void mlp_kernel(const float* __restrict__ z,
                           const float* __restrict__ w0, const float* __restrict__ b0,
                           const float* __restrict__ g0, const float* __restrict__ be0,
                           const float* __restrict__ m0, const float* __restrict__ v0,
                           const float* __restrict__ w1, const float* __restrict__ b1,
                           const float* __restrict__ g1, const float* __restrict__ be1,
                           const float* __restrict__ m1, const float* __restrict__ v1) {
    __shared__ float zr[20];
    __shared__ float xr[128];
    int b = blockIdx.x, h = threadIdx.x;
    if (h < 20) zr[h] = z[b * 20 + h];
    __syncthreads();
    float acc = b0[h];
#pragma unroll
    for (int k = 0; k < 20; k++) acc = fmaf(zr[k], w0[k * 128 + h], acc);
    acc = (acc - m0[h]) * rsqrtf(v0[h] + 1e-3f) * g0[h] + be0[h];
    xr[h] = fmaxf(acc, 0.f);
    __syncthreads();
    float a0 = b1[h], a1 = 0.f, a2 = 0.f, a3 = 0.f;
#pragma unroll 8
    for (int k = 0; k < 128; k += 4) {
        a0 = fmaf(xr[k], w1[k * 128 + h], a0);
        a1 = fmaf(xr[k + 1], w1[(k + 1) * 128 + h], a1);
        a2 = fmaf(xr[k + 2], w1[(k + 2) * 128 + h], a2);
        a3 = fmaf(xr[k + 3], w1[(k + 3) * 128 + h], a3);
    }
    float acc2 = (a0 + a1) + (a2 + a3);
    acc2 = (acc2 - m1[h]) * rsqrtf(v1[h] + 1e-3f) * g1[h] + be1[h];
    g_x2[b * 128 + h] = fmaxf(acc2, 0.f);
}

// ---------------------------------------------------------------------------
// rho GEMM: logits[b][j] = x2[b] . wrho[c,:,o] + brho[c,o],  j = c*1000+o
// ---------------------------------------------------------------------------
__global__ void __launch_bounds__(256, 4)
rho_gemm_kernel(const float* __restrict__ wrho, const float* __restrict__ brho) {
    __shared__ unsigned long long xsp[128 * 8];
    int tid = threadIdx.x;
    int b0r = blockIdx.y * 16;
    for (int i = tid; i < 128 * 8; i += 256) {
        int k = i >> 3, i2 = i & 7;
        float lo = g_x2[(b0r + 2 * i2) * 128 + k];
        float hi = g_x2[(b0r + 2 * i2 + 1) * 128 + k];
        xsp[i] = packf2(lo, hi);
    }
    __syncthreads();
    int j = blockIdx.x * 256 + tid;
    if (j >= 7000) return;
    int c = j / 1000;
    int o = j - c * 1000;
    const float* wb = wrho + c * 128000 + o;
    unsigned long long acc[8];
    {
        float bv = brho[c * 1000 + o];
        unsigned long long b2 = packf2(bv, bv);
#pragma unroll
        for (int i = 0; i < 8; i++) acc[i] = b2;
    }
#pragma unroll 4
    for (int k = 0; k < 128; k++) {
        float wv = wb[k * 1000];
        unsigned long long w2 = packf2(wv, wv);
#pragma unroll
        for (int i = 0; i < 8; i++) ffma2(acc[i], xsp[k * 8 + i], w2);
    }
#pragma unroll
    for (int i = 0; i < 8; i++) {
        float2 t = unpackf2(acc[i]);
        g_logits[(b0r + 2 * i) * 7000 + j] = t.x;
        g_logits[(b0r + 2 * i + 1) * 7000 + j] = t.y;
    }
}

// ---------------------------------------------------------------------------
// theta / pi_drop GEMM (side stream, overlapped with sample).
// blockIdx.z selects matrix. Thread owns a g-pair; weight float2 loads are
// naturally packed; x duplicated in smem; acc[16] u64. grid (49,16,2).
// ---------------------------------------------------------------------------
__global__ void __launch_bounds__(256, 4)
big_gemm_kernel(const float* __restrict__ wr, const float* __restrict__ br,
                const float* __restrict__ wd, const float* __restrict__ bd,
                float* __restrict__ out) {
    __shared__ unsigned long long xdup[128 * 16];   // [k][i] = (x,x)
    int tid = threadIdx.x;
    int b0r = blockIdx.y * 16;
    int which = blockIdx.z;
    for (int t = tid; t < 2048; t += 256) {
        int k = t >> 4, i = t & 15;
        float xv = g_x2[(b0r + i) * 128 + k];
        xdup[t] = packf2(xv, xv);
    }
    __syncthreads();
    int g = blockIdx.x * 512 + 2 * tid;
    if (g >= 25000) return;
    const float* wsel = which ? wd : wr;
    const float* bsel = which ? bd : br;
    unsigned long long acc[16];
    {
        unsigned long long b2 = *(const unsigned long long*)(bsel + g);
#pragma unroll
        for (int i = 0; i < 16; i++) acc[i] = b2;
    }
    const float* wp = wsel + g;
#pragma unroll 8
    for (int k = 0; k < 128; k++) {
        unsigned long long w2 = *(const unsigned long long*)(wp + k * 25000);
        const ulonglong2* xv = (const ulonglong2*)&xdup[k * 16];
#pragma unroll
        for (int i2 = 0; i2 < 8; i2++) {
            ulonglong2 x2p = xv[i2];
            ffma2(acc[2 * i2], x2p.x, w2);
            ffma2(acc[2 * i2 + 1], x2p.y, w2);
        }
    }
    if (which == 0) {
#pragma unroll
        for (int i = 0; i < 16; i++) {
            float2 t = unpackf2(acc[i]);
            *(float2*)&out[6400000 + (b0r + i) * 25000 + g] =
                make_float2(expf(t.x), expf(t.y));
        }
    } else {
#pragma unroll
        for (int i = 0; i < 16; i++) {
            *(unsigned long long*)&out[12800000 + (b0r + i) * 25000 + g] = acc[i];
        }
    }
}

// ---------------------------------------------------------------------------
// Sample kernel: inline rho-softmax + threefry gumbel argmax.
// Fast path uses __logf (MUFU) for the gumbel weights; if the winner's margin
// over any rival is < 1e-4 (100x the __logf error bound), the thread redoes
// the whole decision with exact logf, reproducing the reference argmax and
// tie handling bit-for-bit. Slow-path rate ~0.06% of threads.
// ---------------------------------------------------------------------------
__global__ void __launch_bounds__(256)
sample_kernel(const float* __restrict__ ws, const float* __restrict__ bs,
              float* __restrict__ out) {
    __shared__ float sp[12 * 7];
    __shared__ float spo[256 * 7];
    int tid = threadIdx.x;
    int g0 = blockIdx.x * 256;
    int b = blockIdx.y;                  // 0..255
    int nvalid = min(256, 25000 - g0);
    int bin0 = g0 / 25;
    int nbins = (g0 + nvalid - 1) / 25 - bin0 + 1;  // <= 11
    int npl = nbins * 7;
    for (int i = tid; i < npl; i += 256) {
        int bl = i / 7, c = i - bl * 7;
        sp[i] = g_logits[b * 7000 + c * 1000 + bin0 + bl];
    }
    __syncthreads();
    if (tid < nbins) {
        float v[7];
        float mx = -1e30f;
#pragma unroll
        for (int c = 0; c < 7; c++) { v[c] = sp[tid * 7 + c]; mx = fmaxf(mx, v[c]); }
        float s = 0.f;
#pragma unroll
        for (int c = 0; c < 7; c++) { v[c] = expf(v[c] - mx); s += v[c]; }
        float inv = 1.f / s;
#pragma unroll
        for (int c = 0; c < 7; c++) sp[tid * 7 + c] = v[c] * inv;
    }
    __syncthreads();
    if (tid < nvalid) {
        int g = g0 + tid;
        int binl = g / 25 - bin0;
        const float* p = &sp[binl * 7];
        unsigned base = (unsigned)(b * 25000 + g) * 7u;
        float a[7], w[7];
#pragma unroll
        for (int c = 0; c < 7; c++) {
            unsigned o0, o1;
            tf2x32(0u, base + (unsigned)c, o0, o1);
            float u = bits_to_uniform(o0 ^ o1);
            w[c] = 1e-20f - __logf(u + 1e-20f);   // > 0, fast log
            float pc = p[c];
            spo[tid * 7 + c] = pc;
            a[c] = pc + 1e-20f;                    // > 0
        }
        // fast argmax of a/w via cross-multiplication (w > 0)
        int bb = 0;
#pragma unroll
        for (int c = 1; c < 7; c++) {
            if (a[c] * w[bb] > a[bb] * w[c]) bb = c;
        }
        float abb = a[bb], wbb = w[bb];
        bool close = false;
#pragma unroll
        for (int c = 0; c < 7; c++) {
            if (c != bb) close |= !(abb * w[c] > a[c] * wbb * (1.0f + 1e-4f));
        }
        float s;
        if (!close) {
            s = (float)bb;
        } else {
            // exact recompute: logf weights, argmax + reference-style tie sum
            float we[7];
#pragma unroll
            for (int c = 0; c < 7; c++) {
                unsigned o0, o1;
                tf2x32(0u, base + (unsigned)c, o0, o1);
                float u = bits_to_uniform(o0 ^ o1);
                we[c] = 1e-20f - logf(u + 1e-20f);
            }
            int be = 0;
#pragma unroll
            for (int c = 1; c < 7; c++) {
                if (a[c] * we[be] > a[be] * we[c]) be = c;
            }
            float abe = a[be], wbe = we[be];
            s = 0.f;
#pragma unroll
            for (int c = 0; c < 7; c++) {
                if (a[c] * wbe == abe * we[c]) s += (float)c;
            }
        }
        float wsg = ws[g], bsg = bs[g];
        out[b * 25000 + g] = 1.f / (1.f + __expf(-(s * wsg + bsg)));
        out[19200000 + b * 25000 + g] = s;
    }
    __syncthreads();
    int tot = nvalid * 7;
    float* pib = out + 25600000u + (unsigned)(b * 25000 + g0) * 7u;
    for (int i = tid; i < tot; i += 256) {
        pib[i] = spo[i];
    }
}

// ---------------------------------------------------------------------------
extern "C" void kernel_launch(void* const* d_in, const int* in_sizes, int n_in,
                              void* d_out, int out_size) {
    const float* z    = (const float*)d_in[0];
    const float* w0   = (const float*)d_in[1];
    const float* b0   = (const float*)d_in[2];
    const float* g0   = (const float*)d_in[3];
    const float* be0  = (const float*)d_in[4];
    const float* m0   = (const float*)d_in[5];
    const float* v0   = (const float*)d_in[6];
    const float* w1   = (const float*)d_in[7];
    const float* b1   = (const float*)d_in[8];
    const float* g1   = (const float*)d_in[9];
    const float* be1  = (const float*)d_in[10];
    const float* m1   = (const float*)d_in[11];
    const float* v1   = (const float*)d_in[12];
    const float* wr   = (const float*)d_in[13];
    const float* br   = (const float*)d_in[14];
    const float* wd   = (const float*)d_in[15];
    const float* bd   = (const float*)d_in[16];
    const float* wrho = (const float*)d_in[17];
    const float* brho = (const float*)d_in[18];
    const float* wsc  = (const float*)d_in[19];
    const float* bsc  = (const float*)d_in[20];
    float* out = (float*)d_out;

    // main stream: mlp -> rho_gemm -> sample
    mlp_kernel<<<256, 128>>>(z, w0, b0, g0, be0, m0, v0, w1, b1, g1, be1, m1, v1);
    // fork side stream after mlp for the big GEMM (independent of rho/sample)
    cudaEventRecord(g_sx.e0, 0);
    cudaStreamWaitEvent(g_sx.s1, g_sx.e0, 0);
    big_gemm_kernel<<<dim3(49, 16, 2), 256, 0, g_sx.s1>>>(wr, br, wd, bd, out);
    rho_gemm_kernel<<<dim3(28, 16), 256>>>(wrho, brho);
    sample_kernel<<<dim3(98, 256), 256>>>(wsc, bsc, out);
    // join
    cudaEventRecord(g_sx.e1, g_sx.s1);
    cudaStreamWaitEvent(0, g_sx.e1, 0);
}

// round 9
// speedup vs baseline: 1.5011x; 1.1093x over previous
#include <cuda_runtime.h>
#include <math.h>

// Problem constants
// B=256, LAT=20, HID=128, G=25000, BIN=25, C=7, GB=1000
// Output layout (concatenated f32):
//   mu      [256,25000]      @ 0
//   theta   [256,25000]      @ 6,400,000
//   pi_drop [256,25000]      @ 12,800,000
//   sample  [256,25000]      @ 19,200,000
//   pi      [256,25000,7]    @ 25,600,000   (total 70,400,000)

static __device__ float g_x2[256 * 128];
static __device__ float g_logits[256 * 7000];     // rho logits [b][c*1000+o]

#define GEMM_TILES 1568        // 49 gx * 16 btiles * 2 matrices
#define GEMM_BLOCKS 296        // 2 per SM -> half the register file

// Side stream + events for gemm/sample overlap (created pre-capture; streams
// and events are context resources, not device memory).
namespace {
struct HxStreams {
    cudaStream_t s1 = nullptr;
    cudaEvent_t e0 = nullptr, e1 = nullptr;
    HxStreams() {
        cudaStreamCreateWithFlags(&s1, cudaStreamNonBlocking);
        cudaEventCreateWithFlags(&e0, cudaEventDisableTiming);
        cudaEventCreateWithFlags(&e1, cudaEventDisableTiming);
    }
};
HxStreams g_sx;
}

// ---------------------------------------------------------------------------
// packed f32x2 helpers
// ---------------------------------------------------------------------------
__device__ __forceinline__ unsigned long long packf2(float lo, float hi) {
    unsigned long long r;
    asm("mov.b64 %0, {%1, %2};" : "=l"(r) : "f"(lo), "f"(hi));
    return r;
}
__device__ __forceinline__ float2 unpackf2(unsigned long long v) {
    float lo, hi;
    asm("mov.b64 {%0, %1}, %2;" : "=f"(lo), "=f"(hi) : "l"(v));
    return make_float2(lo, hi);
}
__device__ __forceinline__ void ffma2(unsigned long long& d, unsigned long long a,
                                      unsigned long long b) {
    asm("fma.rn.f32x2 %0, %1, %2, %0;" : "+l"(d) : "l"(a), "l"(b));
}

// ---------------------------------------------------------------------------
// Threefry-2x32, 20 rounds, key = (0, 42), partitionable mode
// ---------------------------------------------------------------------------
__device__ __forceinline__ void tf2x32(unsigned x0, unsigned x1,
                                       unsigned& o0, unsigned& o1) {
    const unsigned K0 = 0u;
    const unsigned K1 = 42u;
    const unsigned K2 = 0x1BD11BDAu ^ 0u ^ 42u;
    x0 += K0; x1 += K1;
#define TF_R(r) { x0 += x1; x1 = __funnelshift_l(x1, x1, r); x1 ^= x0; }
    TF_R(13) TF_R(15) TF_R(26) TF_R(6)
    x0 += K1; x1 += K2 + 1u;
    TF_R(17) TF_R(29) TF_R(16) TF_R(24)
    x0 += K2; x1 += K0 + 2u;
    TF_R(13) TF_R(15) TF_R(26) TF_R(6)
    x0 += K0; x1 += K1 + 3u;
    TF_R(17) TF_R(29) TF_R(16) TF_R(24)
    x0 += K1; x1 += K2 + 4u;
    TF_R(13) TF_R(15) TF_R(26) TF_R(6)
    x0 += K2; x1 += K0 + 5u;
#undef TF_R
    o0 = x0; o1 = x1;
}

__device__ __forceinline__ float bits_to_uniform(unsigned bits) {
    return __uint_as_float((bits >> 9) | 0x3f800000u) - 1.0f;
}

// ---------------------------------------------------------------------------
// Fused MLP: x2 = relu(bn(relu(bn(z@w0+b0)) @ w1 + b1))
// ---------------------------------------------------------------------------
__global__ void mlp_kernel(const float* __restrict__ z,
                           const float* __restrict__ w0, const float* __restrict__ b0,
                           const float* __restrict__ g0, const float* __restrict__ be0,
                           const float* __restrict__ m0, const float* __restrict__ v0,
                           const float* __restrict__ w1, const float* __restrict__ b1,
                           const float* __restrict__ g1, const float* __restrict__ be1,
                           const float* __restrict__ m1, const float* __restrict__ v1) {
    __shared__ float zr[20];
    __shared__ float xr[128];
    int b = blockIdx.x, h = threadIdx.x;
    if (h < 20) zr[h] = z[b * 20 + h];
    __syncthreads();
    float acc = b0[h];
#pragma unroll
    for (int k = 0; k < 20; k++) acc = fmaf(zr[k], w0[k * 128 + h], acc);
    acc = (acc - m0[h]) * rsqrtf(v0[h] + 1e-3f) * g0[h] + be0[h];
    xr[h] = fmaxf(acc, 0.f);
    __syncthreads();
    float a0 = b1[h], a1 = 0.f, a2 = 0.f, a3 = 0.f;
#pragma unroll 8
    for (int k = 0; k < 128; k += 4) {
        a0 = fmaf(xr[k], w1[k * 128 + h], a0);
        a1 = fmaf(xr[k + 1], w1[(k + 1) * 128 + h], a1);
        a2 = fmaf(xr[k + 2], w1[(k + 2) * 128 + h], a2);
        a3 = fmaf(xr[k + 3], w1[(k + 3) * 128 + h], a3);
    }
    float acc2 = (a0 + a1) + (a2 + a3);
    acc2 = (acc2 - m1[h]) * rsqrtf(v1[h] + 1e-3f) * g1[h] + be1[h];
    g_x2[b * 128 + h] = fmaxf(acc2, 0.f);
}

// ---------------------------------------------------------------------------
// rho GEMM: logits[b][j] = x2[b] . wrho[c,:,o] + brho[c,o],  j = c*1000+o
// ---------------------------------------------------------------------------
__global__ void __launch_bounds__(256, 4)
rho_gemm_kernel(const float* __restrict__ wrho, const float* __restrict__ brho) {
    __shared__ unsigned long long xsp[128 * 8];
    int tid = threadIdx.x;
    int b0r = blockIdx.y * 16;
    for (int i = tid; i < 128 * 8; i += 256) {
        int k = i >> 3, i2 = i & 7;
        float lo = g_x2[(b0r + 2 * i2) * 128 + k];
        float hi = g_x2[(b0r + 2 * i2 + 1) * 128 + k];
        xsp[i] = packf2(lo, hi);
    }
    __syncthreads();
    int j = blockIdx.x * 256 + tid;
    if (j >= 7000) return;
    int c = j / 1000;
    int o = j - c * 1000;
    const float* wb = wrho + c * 128000 + o;
    unsigned long long acc[8];
    {
        float bv = brho[c * 1000 + o];
        unsigned long long b2 = packf2(bv, bv);
#pragma unroll
        for (int i = 0; i < 8; i++) acc[i] = b2;
    }
#pragma unroll 4
    for (int k = 0; k < 128; k++) {
        float wv = wb[k * 1000];
        unsigned long long w2 = packf2(wv, wv);
#pragma unroll
        for (int i = 0; i < 8; i++) ffma2(acc[i], xsp[k * 8 + i], w2);
    }
#pragma unroll
    for (int i = 0; i < 8; i++) {
        float2 t = unpackf2(acc[i]);
        g_logits[(b0r + 2 * i) * 7000 + j] = t.x;
        g_logits[(b0r + 2 * i + 1) * 7000 + j] = t.y;
    }
}

// ---------------------------------------------------------------------------
// Persistent theta / pi_drop GEMM: 296 blocks (2/SM, half the register file),
// each loops over tiles. Co-resides with sample_kernel on every SM; its
// memory-latency idle time is hidden under sample's issue pressure.
// Tile t: which = t&1 (0=theta exp, 1=pi_drop), gx = (t>>1)%49,
//         b0r = ((t>>1)/49)*16.
// ---------------------------------------------------------------------------
__global__ void __launch_bounds__(256, 4)
big_gemm_kernel(const float* __restrict__ wr, const float* __restrict__ br,
                const float* __restrict__ wd, const float* __restrict__ bd,
                float* __restrict__ out) {
    __shared__ unsigned long long xdup[128 * 16];   // [k][i] = (x,x)
    int tid = threadIdx.x;
    for (int t = blockIdx.x; t < GEMM_TILES; t += GEMM_BLOCKS) {
        int which = t & 1;
        int tile = t >> 1;
        int gx = tile % 49;
        int b0r = (tile / 49) * 16;
        __syncthreads();   // protect smem reuse across iterations
        for (int s = tid; s < 2048; s += 256) {
            int k = s >> 4, i = s & 15;
            float xv = g_x2[(b0r + i) * 128 + k];
            xdup[s] = packf2(xv, xv);
        }
        __syncthreads();
        int g = gx * 512 + 2 * tid;
        if (g < 25000) {
            const float* wsel = which ? wd : wr;
            const float* bsel = which ? bd : br;
            unsigned long long acc[16];
            {
                unsigned long long b2 = *(const unsigned long long*)(bsel + g);
#pragma unroll
                for (int i = 0; i < 16; i++) acc[i] = b2;
            }
            const float* wp = wsel + g;
#pragma unroll 8
            for (int k = 0; k < 128; k++) {
                unsigned long long w2 = *(const unsigned long long*)(wp + k * 25000);
                const ulonglong2* xv = (const ulonglong2*)&xdup[k * 16];
#pragma unroll
                for (int i2 = 0; i2 < 8; i2++) {
                    ulonglong2 x2p = xv[i2];
                    ffma2(acc[2 * i2], x2p.x, w2);
                    ffma2(acc[2 * i2 + 1], x2p.y, w2);
                }
            }
            if (which == 0) {
#pragma unroll
                for (int i = 0; i < 16; i++) {
                    float2 tt = unpackf2(acc[i]);
                    *(float2*)&out[6400000 + (b0r + i) * 25000 + g] =
                        make_float2(expf(tt.x), expf(tt.y));
                }
            } else {
#pragma unroll
                for (int i = 0; i < 16; i++) {
                    *(unsigned long long*)&out[12800000 + (b0r + i) * 25000 + g] = acc[i];
                }
            }
        }
    }
}

// ---------------------------------------------------------------------------
// Sample kernel: inline rho-softmax + threefry gumbel argmax.
// Fast path __logf; exact logf fallback when winner margin < 1e-4.
// pi copy-out via float4 (alignment: (b*25000+g0) % 4 == 0 -> *7 % 4 == 0).
// ---------------------------------------------------------------------------
__global__ void __launch_bounds__(256)
sample_kernel(const float* __restrict__ ws, const float* __restrict__ bs,
              float* __restrict__ out) {
    __shared__ float sp[12 * 7];
    __shared__ float spo[256 * 7];
    int tid = threadIdx.x;
    int g0 = blockIdx.x * 256;
    int b = blockIdx.y;                  // 0..255
    int nvalid = min(256, 25000 - g0);
    int bin0 = g0 / 25;
    int nbins = (g0 + nvalid - 1) / 25 - bin0 + 1;  // <= 11
    int npl = nbins * 7;
    for (int i = tid; i < npl; i += 256) {
        int bl = i / 7, c = i - bl * 7;
        sp[i] = g_logits[b * 7000 + c * 1000 + bin0 + bl];
    }
    __syncthreads();
    if (tid < nbins) {
        float v[7];
        float mx = -1e30f;
#pragma unroll
        for (int c = 0; c < 7; c++) { v[c] = sp[tid * 7 + c]; mx = fmaxf(mx, v[c]); }
        float s = 0.f;
#pragma unroll
        for (int c = 0; c < 7; c++) { v[c] = expf(v[c] - mx); s += v[c]; }
        float inv = 1.f / s;
#pragma unroll
        for (int c = 0; c < 7; c++) sp[tid * 7 + c] = v[c] * inv;
    }
    __syncthreads();
    if (tid < nvalid) {
        int g = g0 + tid;
        int binl = g / 25 - bin0;
        const float* p = &sp[binl * 7];
        unsigned base = (unsigned)(b * 25000 + g) * 7u;
        float a[7], w[7];
#pragma unroll
        for (int c = 0; c < 7; c++) {
            unsigned o0, o1;
            tf2x32(0u, base + (unsigned)c, o0, o1);
            float u = bits_to_uniform(o0 ^ o1);
            w[c] = 1e-20f - __logf(u + 1e-20f);   // > 0, fast log
            float pc = p[c];
            spo[tid * 7 + c] = pc;
            a[c] = pc + 1e-20f;                    // > 0
        }
        int bb = 0;
#pragma unroll
        for (int c = 1; c < 7; c++) {
            if (a[c] * w[bb] > a[bb] * w[c]) bb = c;
        }
        float abb = a[bb], wbb = w[bb];
        bool close = false;
#pragma unroll
        for (int c = 0; c < 7; c++) {
            if (c != bb) close |= !(abb * w[c] > a[c] * wbb * (1.0f + 1e-4f));
        }
        float s;
        if (!close) {
            s = (float)bb;
        } else {
            float we[7];
#pragma unroll
            for (int c = 0; c < 7; c++) {
                unsigned o0, o1;
                tf2x32(0u, base + (unsigned)c, o0, o1);
                float u = bits_to_uniform(o0 ^ o1);
                we[c] = 1e-20f - logf(u + 1e-20f);
            }
            int be = 0;
#pragma unroll
            for (int c = 1; c < 7; c++) {
                if (a[c] * we[be] > a[be] * we[c]) be = c;
            }
            float abe = a[be], wbe = we[be];
            s = 0.f;
#pragma unroll
            for (int c = 0; c < 7; c++) {
                if (a[c] * wbe == abe * we[c]) s += (float)c;
            }
        }
        float wsg = ws[g], bsg = bs[g];
        out[b * 25000 + g] = 1.f / (1.f + __expf(-(s * wsg + bsg)));
        out[19200000 + b * 25000 + g] = s;
    }
    __syncthreads();
    int tot4 = (nvalid * 7) >> 2;       // nvalid*7 divisible by 4 (nvalid 256 or 168)
    float4* pib4 = (float4*)(out + 25600000u + (unsigned)(b * 25000 + g0) * 7u);
    const float4* spo4 = (const float4*)spo;
    for (int i = tid; i < tot4; i += 256) {
        pib4[i] = spo4[i];
    }
}

// ---------------------------------------------------------------------------
extern "C" void kernel_launch(void* const* d_in, const int* in_sizes, int n_in,
                              void* d_out, int out_size) {
    const float* z    = (const float*)d_in[0];
    const float* w0   = (const float*)d_in[1];
    const float* b0   = (const float*)d_in[2];
    const float* g0   = (const float*)d_in[3];
    const float* be0  = (const float*)d_in[4];
    const float* m0   = (const float*)d_in[5];
    const float* v0   = (const float*)d_in[6];
    const float* w1   = (const float*)d_in[7];
    const float* b1   = (const float*)d_in[8];
    const float* g1   = (const float*)d_in[9];
    const float* be1  = (const float*)d_in[10];
    const float* m1   = (const float*)d_in[11];
    const float* v1   = (const float*)d_in[12];
    const float* wr   = (const float*)d_in[13];
    const float* br   = (const float*)d_in[14];
    const float* wd   = (const float*)d_in[15];
    const float* bd   = (const float*)d_in[16];
    const float* wrho = (const float*)d_in[17];
    const float* brho = (const float*)d_in[18];
    const float* wsc  = (const float*)d_in[19];
    const float* bsc  = (const float*)d_in[20];
    float* out = (float*)d_out;

    // main stream: mlp -> rho_gemm -> sample ; side stream: persistent big_gemm
    mlp_kernel<<<256, 128>>>(z, w0, b0, g0, be0, m0, v0, w1, b1, g1, be1, m1, v1);
    cudaEventRecord(g_sx.e0, 0);
    cudaStreamWaitEvent(g_sx.s1, g_sx.e0, 0);
    big_gemm_kernel<<<GEMM_BLOCKS, 256, 0, g_sx.s1>>>(wr, br, wd, bd, out);
    rho_gemm_kernel<<<dim3(28, 16), 256>>>(wrho, brho);
    sample_kernel<<<dim3(98, 256), 256>>>(wsc, bsc, out);
    cudaEventRecord(g_sx.e1, g_sx.s1);
    cudaStreamWaitEvent(0, g_sx.e1, 0);
}